// round 6
// baseline (speedup 1.0000x reference)
#include <cuda_runtime.h>
#include <cuda_bf16.h>
#include <cstdint>

// Problem constants
#define TT 512
#define BB 32
#define EE 1024
#define HH 512
#define CC 24
#define NGATE 2048          // 4*HH
#define NPROJ 4096          // 2 dirs * 4H
#define MROWS (TT*BB)       // 16384

// -------------------- scratch (device globals; no allocation) --------------------
__device__ float g_xt[MROWS * EE];          // layer-0 input  [t][b][e]
__device__ float g_inproj[MROWS * NPROJ];   // x@Wih^T + bias [t][b][dir*2048 + gate*512 + j]
__device__ float g_hout0[MROWS * 1024];     // layer-0 output [t][b][dir*512 + j]
__device__ float g_hout1[MROWS * 1024];     // layer-1 output
__device__ float g_h[2 * 2 * BB * HH];      // [parity][dir][b*H + j]
__device__ unsigned g_bar_cnt[2];           // per-dir grid barrier
__device__ unsigned g_bar_gen[2];

// -------------------- embedding gather --------------------
__global__ void gather_kernel(const int* __restrict__ x, const float* __restrict__ emb) {
    int idx = blockIdx.x * blockDim.x + threadIdx.x;   // over MROWS * (EE/4)
    int e4 = idx & 255;            // EE/4 = 256
    int tb = idx >> 8;             // t*BB + b
    int b  = tb & 31;
    int t  = tb >> 5;
    int tok = x[b * TT + t];
    float4 v = ((const float4*)(emb + (size_t)tok * EE))[e4];
    ((float4*)(g_xt + (size_t)tb * EE))[e4] = v;
}

// -------------------- SGEMM: C[m][n] = sum_k A[m][k]*W[n][k] + b1[n]+b2[n] --------------------
__global__ __launch_bounds__(256, 2)
void sgemm_tn(const float* __restrict__ W,
              const float* __restrict__ b1, const float* __restrict__ b2,
              int a_sel) {
    const int K = 1024, N = NPROJ;
    const float* __restrict__ A = a_sel ? g_hout0 : g_xt;
    float* __restrict__ Cmat = g_inproj;

    __shared__ float As[16][132];
    __shared__ float Bs[16][132];

    int tid = threadIdx.x;
    int m0 = blockIdx.y * 128;
    int n0 = blockIdx.x * 128;
    int tx = tid & 15, ty = tid >> 4;

    float acc[8][8];
#pragma unroll
    for (int i = 0; i < 8; i++)
#pragma unroll
        for (int j = 0; j < 8; j++) acc[i][j] = 0.f;

    for (int k0 = 0; k0 < K; k0 += 16) {
#pragma unroll
        for (int p = 0; p < 2; p++) {
            int f  = p * 256 + tid;
            int r  = f >> 2;
            int kk = (f & 3) * 4;
            float4 va = *(const float4*)(A + (size_t)(m0 + r) * K + k0 + kk);
            As[kk + 0][r] = va.x; As[kk + 1][r] = va.y;
            As[kk + 2][r] = va.z; As[kk + 3][r] = va.w;
            float4 vb = *(const float4*)(W + (size_t)(n0 + r) * K + k0 + kk);
            Bs[kk + 0][r] = vb.x; Bs[kk + 1][r] = vb.y;
            Bs[kk + 2][r] = vb.z; Bs[kk + 3][r] = vb.w;
        }
        __syncthreads();
#pragma unroll
        for (int k = 0; k < 16; k++) {
            float a[8], bb[8];
#pragma unroll
            for (int i = 0; i < 8; i++) a[i] = As[k][ty * 8 + i];
#pragma unroll
            for (int j = 0; j < 8; j++) bb[j] = Bs[k][tx * 8 + j];
#pragma unroll
            for (int i = 0; i < 8; i++)
#pragma unroll
                for (int j = 0; j < 8; j++) acc[i][j] += a[i] * bb[j];
        }
        __syncthreads();
    }

#pragma unroll
    for (int i = 0; i < 8; i++) {
        int m = m0 + ty * 8 + i;
#pragma unroll
        for (int j = 0; j < 8; j++) {
            int n = n0 + tx * 8 + j;
            Cmat[(size_t)m * NPROJ + n] = acc[i][j] + b1[n] + b2[n];
        }
    }
    (void)N;
}

// -------------------- zero h state + reset barriers --------------------
__global__ void zero_state_kernel() {
    int i = blockIdx.x * blockDim.x + threadIdx.x;
    if (i < 2 * 2 * BB * HH) g_h[i] = 0.f;
    if (i < 2) { g_bar_cnt[i] = 0u; g_bar_gen[i] = 0u; }
}

// -------------------- persistent bi-LSTM layer kernel --------------------
// grid: 128 blocks = dir(2) x jtile(64; 8 j each). block: 256 = 8 warps.
// Warp w owns j = jt*8 + w, lanes = 32 batches. Whh slice stays in smem all steps.
// Dynamic smem: ws[32][512] (64KB) + hs[32][516] (66KB) + ips[32][33] (4.2KB)
#define L_SMEM_FLOATS (32*512 + 32*516 + 32*33)
#define L_SMEM_BYTES  (L_SMEM_FLOATS * 4)

__global__ __launch_bounds__(256, 1)
void lstm_layer_persist(const float* __restrict__ whh_l,  // [2][4H][H]
                        int out_sel) {
    extern __shared__ float smem[];
    float* ws  = smem;                    // [row=g*8+jl][k]  (32 x 512)
    float* hs  = smem + 32 * 512;         // [b][k] padded    (32 x 516)
    float* ips = smem + 32 * 512 + 32 * 516;  // [row][b]     (32 x 33)

    const int dir = (int)blockIdx.x >> 6;
    const int jt  = (int)blockIdx.x & 63;
    const int tid = threadIdx.x;
    const int w   = tid >> 5;             // warp 0..7 -> local j
    const int b   = tid & 31;             // lane -> batch
    const int j   = jt * 8 + w;

    float* __restrict__ hout = out_sel ? g_hout1 : g_hout0;
    const float* __restrict__ wbase = whh_l + (size_t)dir * 4 * HH * HH;

    // ---- load Whh slice once: rows g*8+jl -> whh row g*512 + jt*8 + jl ----
    for (int i = tid; i < 32 * 128; i += 256) {       // float4 index
        int row = i >> 7;                // 0..31
        int k4  = i & 127;
        int g   = row >> 3, jl = row & 7;
        float4 v = *(const float4*)(wbase + (size_t)(g * HH + jt * 8 + jl) * HH + k4 * 4);
        *(float4*)(ws + row * 512 + k4 * 4) = v;
    }
    __syncthreads();

    // ip staging mapping (per thread, fixed): tid -> (bb, gg, j4)
    const int sb  = tid >> 3;
    const int sg  = (tid >> 1) & 3;
    const int sj4 = tid & 1;

    float c_reg = 0.f;

    for (int t = 0; t < TT; t++) {
        const int p  = t & 1;
        const int tt = dir ? (TT - 1 - t) : t;

        // ---- grid barrier (per direction) so g_h[p] from step t-1 is complete ----
        if (t > 0) {
            __syncthreads();
            if (tid == 0) {
                __threadfence();
                unsigned a = atomicAdd(&g_bar_cnt[dir], 1u);
                if (a == 63u) {
                    g_bar_cnt[dir] = 0u;
                    __threadfence();
                    atomicExch(&g_bar_gen[dir], (unsigned)t);
                } else {
                    while (*(volatile unsigned*)&g_bar_gen[dir] < (unsigned)t) { }
                }
                __threadfence();
            }
            __syncthreads();
        }

        // ---- stage h(t-1) for own dir into smem: hs[b][k] ----
        {
            const float* hsrc = g_h + (size_t)(p * 2 + dir) * (BB * HH);
            for (int i = tid; i < 32 * 128; i += 256) {
                int bb = i >> 7, k4 = i & 127;
                float4 v = *(const float4*)(hsrc + bb * 512 + k4 * 4);
                *(float4*)(hs + bb * 516 + k4 * 4) = v;
            }
        }
        // ---- stage input-projection tile: ips[row][b] ----
        {
            const float* ipg = g_inproj + ((size_t)tt * 32 + sb) * NPROJ
                               + dir * NGATE + sg * HH + jt * 8 + sj4 * 4;
            float4 v = *(const float4*)ipg;
            int rbase = sg * 8 + sj4 * 4;
            ips[(rbase + 0) * 33 + sb] = v.x;
            ips[(rbase + 1) * 33 + sb] = v.y;
            ips[(rbase + 2) * 33 + sb] = v.z;
            ips[(rbase + 3) * 33 + sb] = v.w;
        }
        __syncthreads();

        // ---- compute 4 gate dots for (j, b) ----
        const float4* hp  = (const float4*)(hs + b * 516);
        const float4* w0p = (const float4*)(ws + (0 * 8 + w) * 512);
        const float4* w1p = (const float4*)(ws + (1 * 8 + w) * 512);
        const float4* w2p = (const float4*)(ws + (2 * 8 + w) * 512);
        const float4* w3p = (const float4*)(ws + (3 * 8 + w) * 512);

        float a0 = 0.f, a0b = 0.f, a1 = 0.f, a1b = 0.f;
        float a2 = 0.f, a2b = 0.f, a3 = 0.f, a3b = 0.f;
#pragma unroll 8
        for (int k4 = 0; k4 < 128; k4++) {
            float4 h4 = hp[k4];
            float4 w0 = w0p[k4];
            float4 w1 = w1p[k4];
            float4 w2 = w2p[k4];
            float4 w3 = w3p[k4];
            a0  = fmaf(h4.x, w0.x, a0);  a0b = fmaf(h4.y, w0.y, a0b);
            a0  = fmaf(h4.z, w0.z, a0);  a0b = fmaf(h4.w, w0.w, a0b);
            a1  = fmaf(h4.x, w1.x, a1);  a1b = fmaf(h4.y, w1.y, a1b);
            a1  = fmaf(h4.z, w1.z, a1);  a1b = fmaf(h4.w, w1.w, a1b);
            a2  = fmaf(h4.x, w2.x, a2);  a2b = fmaf(h4.y, w2.y, a2b);
            a2  = fmaf(h4.z, w2.z, a2);  a2b = fmaf(h4.w, w2.w, a2b);
            a3  = fmaf(h4.x, w3.x, a3);  a3b = fmaf(h4.y, w3.y, a3b);
            a3  = fmaf(h4.z, w3.z, a3);  a3b = fmaf(h4.w, w3.w, a3b);
        }

        float gi = a0 + a0b + ips[(0 * 8 + w) * 33 + b];
        float gf = a1 + a1b + ips[(1 * 8 + w) * 33 + b];
        float gg = a2 + a2b + ips[(2 * 8 + w) * 33 + b];
        float go = a3 + a3b + ips[(3 * 8 + w) * 33 + b];

        gi = 1.f / (1.f + expf(-gi));
        gf = 1.f / (1.f + expf(-gf));
        gg = tanhf(gg);
        go = 1.f / (1.f + expf(-go));

        c_reg = gf * c_reg + gi * gg;
        float h = go * tanhf(c_reg);

        g_h[(size_t)((p ^ 1) * 2 + dir) * (BB * HH) + b * 512 + j] = h;
        hout[((size_t)tt * 32 + b) * 1024 + dir * HH + j] = h;
    }
}

// -------------------- FC: logits[b][t][c] --------------------
__global__ void fc_kernel(const float* __restrict__ fcw, const float* __restrict__ fcb,
                          float* __restrict__ out) {
    int row = blockIdx.x;          // t*BB + b
    int t = row >> 5;
    int b = row & 31;
    int c = threadIdx.x >> 5;      // 0..23
    int lane = threadIdx.x & 31;

    const float4* h4 = (const float4*)(g_hout1 + (size_t)row * 1024);
    const float4* w4 = (const float4*)(fcw + (size_t)c * 1024);
    float s = 0.f;
#pragma unroll 4
    for (int k = lane; k < 256; k += 32) {
        float4 a = h4[k], w = w4[k];
        s += a.x * w.x + a.y * w.y + a.z * w.z + a.w * w.w;
    }
#pragma unroll
    for (int o = 16; o; o >>= 1) s += __shfl_xor_sync(0xffffffffu, s, o);
    if (lane == 0) out[((size_t)b * TT + t) * CC + c] = s + fcb[c];
}

// -------------------- CRF --------------------
__global__ void crf_kernel(const float* __restrict__ em,      // [b][t][c] (= d_out)
                           const int* __restrict__ labels,    // [b][t]
                           const float* __restrict__ st, const float* __restrict__ en,
                           const float* __restrict__ tr, float* __restrict__ loss_out) {
    __shared__ float trs[24][24];
    __shared__ float alpha[32][24];
    __shared__ float anew[32][24];
    __shared__ float logZ[32];
    __shared__ float num[32];

    int tid = threadIdx.x;          // 768 = 32*24
    if (tid < 576) trs[tid / 24][tid % 24] = tr[tid];
    int b = tid / 24;
    int cn = tid % 24;
    __syncthreads();

    alpha[b][cn] = st[cn] + em[(size_t)b * TT * CC + cn];
    __syncthreads();

    for (int t = 1; t < TT; t++) {
        float m = -1e30f;
#pragma unroll
        for (int cp = 0; cp < 24; cp++) m = fmaxf(m, alpha[b][cp] + trs[cp][cn]);
        float s = 0.f;
#pragma unroll
        for (int cp = 0; cp < 24; cp++) s += expf(alpha[b][cp] + trs[cp][cn] - m);
        anew[b][cn] = m + logf(s) + em[(size_t)b * TT * CC + (size_t)t * CC + cn];
        __syncthreads();
        alpha[b][cn] = anew[b][cn];
        __syncthreads();
    }

    if (cn == 0) {
        float m = -1e30f;
        for (int c = 0; c < 24; c++) m = fmaxf(m, alpha[b][c] + en[c]);
        float s = 0.f;
        for (int c = 0; c < 24; c++) s += expf(alpha[b][c] + en[c] - m);
        logZ[b] = m + logf(s);

        int prev = labels[b * TT];
        float nm = st[prev] + em[(size_t)b * TT * CC + prev];
        for (int t = 1; t < TT; t++) {
            int tg = labels[b * TT + t];
            nm += trs[prev][tg] + em[(size_t)b * TT * CC + (size_t)t * CC + tg];
            prev = tg;
        }
        nm += en[prev];
        num[b] = nm;
    }
    __syncthreads();
    if (tid == 0) {
        float L = 0.f;
        for (int bb = 0; bb < 32; bb++) L += logZ[bb] - num[bb];
        loss_out[0] = L;   // -llh
    }
}

// -------------------- launch --------------------
extern "C" void kernel_launch(void* const* d_in, const int* in_sizes, int n_in,
                              void* d_out, int out_size) {
    const int*   x         = (const int*)d_in[0];
    const int*   labels    = (const int*)d_in[1];
    const float* emb       = (const float*)d_in[2];
    const float* w_ih      = (const float*)d_in[3];
    const float* w_hh      = (const float*)d_in[4];
    const float* b_ih      = (const float*)d_in[5];
    const float* b_hh      = (const float*)d_in[6];
    const float* fc_w      = (const float*)d_in[7];
    const float* fc_b      = (const float*)d_in[8];
    const float* crf_start = (const float*)d_in[9];
    const float* crf_end   = (const float*)d_in[10];
    const float* crf_trans = (const float*)d_in[11];
    float* out = (float*)d_out;

    (void)in_sizes; (void)n_in; (void)out_size;

    cudaFuncSetAttribute(lstm_layer_persist,
                         cudaFuncAttributeMaxDynamicSharedMemorySize, L_SMEM_BYTES);

    // 1. embedding gather -> g_xt [t][b][e]
    gather_kernel<<<MROWS, 256>>>(x, emb);

    // 2. per-layer: input-projection GEMM, then persistent recurrence kernel
    for (int l = 0; l < 2; l++) {
        const float* wih_l = w_ih + (size_t)l * 2 * NGATE * EE;   // [2,2048,1024]
        const float* whh_l = w_hh + (size_t)l * 2 * NGATE * HH;   // [2,2048,512]
        const float* bih_l = b_ih + (size_t)l * NPROJ;
        const float* bhh_l = b_hh + (size_t)l * NPROJ;

        sgemm_tn<<<dim3(NPROJ / 128, MROWS / 128), 256>>>(wih_l, bih_l, bhh_l, l);
        zero_state_kernel<<<256, 256>>>();
        lstm_layer_persist<<<128, 256, L_SMEM_BYTES>>>(whh_l, l);
    }

    // 3. FC -> logits straight into d_out as [b][t][c]
    fc_kernel<<<MROWS, 768>>>(fc_w, fc_b, out);

    // 4. CRF loss -> d_out[B*T*C]
    crf_kernel<<<1, 768>>>(out, labels, crf_start, crf_end, crf_trans,
                           out + (size_t)BB * TT * CC);
}

// round 8
// speedup vs baseline: 1.2771x; 1.2771x over previous
#include <cuda_runtime.h>
#include <cuda_bf16.h>
#include <cstdint>

typedef unsigned long long u64;

// Problem constants
#define TT 512
#define BB 32
#define EE 1024
#define HH 512
#define CC 24
#define NGATE 2048          // 4*HH
#define NPROJ 4096          // 2 dirs * 4H
#define MROWS (TT*BB)       // 16384

// -------------------- scratch (device globals; no allocation) --------------------
__device__ __nv_bfloat16 g_x_hi[MROWS * EE];
__device__ __nv_bfloat16 g_x_lo[MROWS * EE];
__device__ __nv_bfloat16 g_h0_hi[MROWS * 1024];
__device__ __nv_bfloat16 g_h0_lo[MROWS * 1024];
__device__ __nv_bfloat16 g_w_hi[2 * NPROJ * EE];
__device__ __nv_bfloat16 g_w_lo[2 * NPROJ * EE];
__device__ float g_inproj[MROWS * NPROJ];   // [t][b][dir*2048 + gate*512 + j]
__device__ float g_hout1[MROWS * 1024];     // layer-1 output [t][b][dir*512+j]
__device__ float g_h[2 * 2 * BB * HH];      // [parity][dir][b*H + j]
__device__ unsigned g_bar_cnt[2];
__device__ unsigned g_bar_gen[2];
__device__ float g_crf_partial[BB];

// -------------------- PTX helpers --------------------
__device__ __forceinline__ uint32_t smem_u32(const void* p) {
    uint32_t a;
    asm("{ .reg .u64 t; cvta.to.shared.u64 t, %1; cvt.u32.u64 %0, t; }" : "=r"(a) : "l"(p));
    return a;
}

#define CP_ASYNC16(dst, src) \
    asm volatile("cp.async.cg.shared.global [%0], [%1], 16;" :: "r"(dst), "l"(src) : "memory")
#define CP_COMMIT() asm volatile("cp.async.commit_group;" ::: "memory")
#define CP_WAIT(n)  asm volatile("cp.async.wait_group %0;" :: "n"(n) : "memory")

// mma.sync m16n8k16 row.col bf16 -> f32 accumulate (sm_80+; valid on plain sm_103)
#define MMA_BF16(d, a, b) \
    asm volatile("mma.sync.aligned.m16n8k16.row.col.f32.bf16.bf16.f32 " \
        "{%0,%1,%2,%3}, {%4,%5,%6,%7}, {%8,%9}, {%0,%1,%2,%3};" \
        : "+f"((d)[0]), "+f"((d)[1]), "+f"((d)[2]), "+f"((d)[3]) \
        : "r"((a)[0]), "r"((a)[1]), "r"((a)[2]), "r"((a)[3]), \
          "r"((b)[0]), "r"((b)[1]))

// packed f32x2 FMA (compiles on sm_103 — verified in R7 log)
#define FMA2(acc, x, y) asm("fma.rn.f32x2 %0, %1, %2, %0;" : "+l"(acc) : "l"(x), "l"(y))
__device__ __forceinline__ float sum2(u64 a) {
    float x, y;
    asm("mov.b64 {%0, %1}, %2;" : "=f"(x), "=f"(y) : "l"(a));
    return x + y;
}

__device__ __forceinline__ uint32_t pack_hi2(float a, float b, float& ra, float& rb) {
    __nv_bfloat16 ha = __float2bfloat16(a), hb = __float2bfloat16(b);
    ra = a - __bfloat162float(ha);
    rb = b - __bfloat162float(hb);
    return (uint32_t)__bfloat16_as_ushort(ha) | ((uint32_t)__bfloat16_as_ushort(hb) << 16);
}
__device__ __forceinline__ uint32_t pack_lo2(float ra, float rb) {
    __nv_bfloat16 la = __float2bfloat16(ra), lb = __float2bfloat16(rb);
    return (uint32_t)__bfloat16_as_ushort(la) | ((uint32_t)__bfloat16_as_ushort(lb) << 16);
}

// -------------------- embedding gather + split --------------------
__global__ void gather_split(const int* __restrict__ x, const float* __restrict__ emb) {
    int idx = blockIdx.x * blockDim.x + threadIdx.x;   // MROWS * 256
    int e4 = idx & 255;
    int tb = idx >> 8;
    int b = tb & 31, t = tb >> 5;
    int tok = x[b * TT + t];
    float4 v = ((const float4*)(emb + (size_t)tok * EE))[e4];
    float r0, r1, r2, r3;
    uint2 hi, lo;
    hi.x = pack_hi2(v.x, v.y, r0, r1);
    hi.y = pack_hi2(v.z, v.w, r2, r3);
    lo.x = pack_lo2(r0, r1);
    lo.y = pack_lo2(r2, r3);
    size_t dst = (size_t)tb * EE + e4 * 4;
    *(uint2*)(g_x_hi + dst) = hi;
    *(uint2*)(g_x_lo + dst) = lo;
}

// -------------------- weight split (both layers) --------------------
__global__ void wconv(const float* __restrict__ w_ih) {
    int idx = blockIdx.x * blockDim.x + threadIdx.x;   // 2*4096*1024/4
    float4 v = ((const float4*)w_ih)[idx];
    float r0, r1, r2, r3;
    uint2 hi, lo;
    hi.x = pack_hi2(v.x, v.y, r0, r1);
    hi.y = pack_hi2(v.z, v.w, r2, r3);
    lo.x = pack_lo2(r0, r1);
    lo.y = pack_lo2(r2, r3);
    size_t dst = (size_t)idx * 4;
    *(uint2*)(g_w_hi + dst) = hi;
    *(uint2*)(g_w_lo + dst) = lo;
}

// -------------------- tensor-core split-bf16 GEMM via mma.sync --------------------
// C[m][n] = sum_k A[m][k]*W[n][k] + b1[n]+b2[n];  M=16384, N=4096, K=1024.
// Block tile 128x128, 8 warps (4 m x 2 n), k16 stages, cp.async double buffer.
// 3 products (hi*hi, hi*lo, lo*hi) into fp32 accumulators.
#define GP 24                       // smem row pitch in bf16 (conflict-free)
#define TILE_B (128 * GP * 2)       // 6144 bytes per tile
#define STAGE_B (4 * TILE_B)        // 24576 bytes per stage
#define GM_SMEM (2 * STAGE_B)       // 49152

__global__ __launch_bounds__(256, 1)
void gemm_mma(int layer, const float* __restrict__ b1, const float* __restrict__ b2) {
    extern __shared__ char gsm[];
    __shared__ float s_bias[128];

    const int tid = threadIdx.x;
    const int lane = tid & 31, wid = tid >> 5;
    const int wm = wid & 3, wn = wid >> 2;          // 4 m-warps x 2 n-warps
    const int g = lane >> 2, tq = lane & 3;
    const int m0 = blockIdx.y * 128, n0 = blockIdx.x * 128;

    const __nv_bfloat16* A_hi = layer ? g_h0_hi : g_x_hi;
    const __nv_bfloat16* A_lo = layer ? g_h0_lo : g_x_lo;
    const __nv_bfloat16* srcs[4];
    srcs[0] = A_hi + (size_t)m0 * 1024;
    srcs[1] = A_lo + (size_t)m0 * 1024;
    srcs[2] = g_w_hi + (size_t)layer * NPROJ * EE + (size_t)n0 * 1024;
    srcs[3] = g_w_lo + (size_t)layer * NPROJ * EE + (size_t)n0 * 1024;

    if (tid < 128) s_bias[tid] = b1[n0 + tid] + b2[n0 + tid];

    const uint32_t sb = smem_u32(gsm);
    const int row  = tid >> 1;       // 0..127
    const int half = tid & 1;        // 16B half of the 32B row chunk

#define LOAD_STAGE(s, kc) do { \
        uint32_t _d = sb + (s) * STAGE_B + row * 48 + half * 16; \
        size_t _go = (size_t)row * 1024 + (size_t)(kc) * 16 + half * 8; \
        CP_ASYNC16(_d + 0 * TILE_B, srcs[0] + _go); \
        CP_ASYNC16(_d + 1 * TILE_B, srcs[1] + _go); \
        CP_ASYNC16(_d + 2 * TILE_B, srcs[2] + _go); \
        CP_ASYNC16(_d + 3 * TILE_B, srcs[3] + _go); \
        CP_COMMIT(); \
    } while (0)

    float acc[2][8][4];
#pragma unroll
    for (int mi = 0; mi < 2; mi++)
#pragma unroll
        for (int ni = 0; ni < 8; ni++)
#pragma unroll
            for (int q = 0; q < 4; q++) acc[mi][ni][q] = 0.f;

    LOAD_STAGE(0, 0);

    for (int kc = 0; kc < 64; kc++) {
        const int s = kc & 1;
        if (kc < 63) { LOAD_STAGE(s ^ 1, kc + 1); CP_WAIT(1); }
        else         { CP_WAIT(0); }
        __syncthreads();

        const char* tAh = gsm + s * STAGE_B + 0 * TILE_B;
        const char* tAl = gsm + s * STAGE_B + 1 * TILE_B;
        const char* tWh = gsm + s * STAGE_B + 2 * TILE_B;
        const char* tWl = gsm + s * STAGE_B + 3 * TILE_B;

        uint32_t a_hi[2][4], a_lo[2][4], b_hi[8][2], b_lo[8][2];
#pragma unroll
        for (int mi = 0; mi < 2; mi++) {
            int rb = wm * 32 + mi * 16 + g;
            int c0 = tq * 2;
            a_hi[mi][0] = *(const uint32_t*)(tAh + (rb * GP + c0) * 2);
            a_hi[mi][1] = *(const uint32_t*)(tAh + ((rb + 8) * GP + c0) * 2);
            a_hi[mi][2] = *(const uint32_t*)(tAh + (rb * GP + c0 + 8) * 2);
            a_hi[mi][3] = *(const uint32_t*)(tAh + ((rb + 8) * GP + c0 + 8) * 2);
            a_lo[mi][0] = *(const uint32_t*)(tAl + (rb * GP + c0) * 2);
            a_lo[mi][1] = *(const uint32_t*)(tAl + ((rb + 8) * GP + c0) * 2);
            a_lo[mi][2] = *(const uint32_t*)(tAl + (rb * GP + c0 + 8) * 2);
            a_lo[mi][3] = *(const uint32_t*)(tAl + ((rb + 8) * GP + c0 + 8) * 2);
        }
#pragma unroll
        for (int ni = 0; ni < 8; ni++) {
            int nr = wn * 64 + ni * 8 + g;
            int c0 = tq * 2;
            b_hi[ni][0] = *(const uint32_t*)(tWh + (nr * GP + c0) * 2);
            b_hi[ni][1] = *(const uint32_t*)(tWh + (nr * GP + c0 + 8) * 2);
            b_lo[ni][0] = *(const uint32_t*)(tWl + (nr * GP + c0) * 2);
            b_lo[ni][1] = *(const uint32_t*)(tWl + (nr * GP + c0 + 8) * 2);
        }

#pragma unroll
        for (int mi = 0; mi < 2; mi++)
#pragma unroll
            for (int ni = 0; ni < 8; ni++) {
                MMA_BF16(acc[mi][ni], a_hi[mi], b_hi[ni]);
                MMA_BF16(acc[mi][ni], a_hi[mi], b_lo[ni]);
                MMA_BF16(acc[mi][ni], a_lo[mi], b_hi[ni]);
            }
        __syncthreads();
    }

    // epilogue: bias + store
#pragma unroll
    for (int mi = 0; mi < 2; mi++) {
        int mg = m0 + wm * 32 + mi * 16 + g;
#pragma unroll
        for (int ni = 0; ni < 8; ni++) {
            int nl = wn * 64 + ni * 8 + tq * 2;
            int ng = n0 + nl;
            float2 v0, v1;
            v0.x = acc[mi][ni][0] + s_bias[nl];
            v0.y = acc[mi][ni][1] + s_bias[nl + 1];
            v1.x = acc[mi][ni][2] + s_bias[nl];
            v1.y = acc[mi][ni][3] + s_bias[nl + 1];
            *(float2*)(g_inproj + (size_t)mg * NPROJ + ng) = v0;
            *(float2*)(g_inproj + (size_t)(mg + 8) * NPROJ + ng) = v1;
        }
    }
#undef LOAD_STAGE
}

// -------------------- zero h state + reset barriers --------------------
__global__ void zero_state_kernel() {
    int i = blockIdx.x * blockDim.x + threadIdx.x;
    if (i < 2 * 2 * BB * HH) g_h[i] = 0.f;
    if (i < 2) { g_bar_cnt[i] = 0u; g_bar_gen[i] = 0u; }
}

// -------------------- persistent bi-LSTM layer kernel (f32x2 FMA) --------------------
#define L_SMEM_FLOATS (32*512 + 32*516 + 32*33)
#define L_SMEM_BYTES  (L_SMEM_FLOATS * 4)

__global__ __launch_bounds__(256, 1)
void lstm_layer_persist(const float* __restrict__ whh_l, int layer) {
    extern __shared__ float smem[];
    float* ws  = smem;                          // [row=g*8+jl][512]
    float* hs  = smem + 32 * 512;               // [b][516]
    float* ips = smem + 32 * 512 + 32 * 516;    // [row][33]

    const int dir = (int)blockIdx.x >> 6;
    const int jt  = (int)blockIdx.x & 63;
    const int tid = threadIdx.x;
    const int w   = tid >> 5;
    const int b   = tid & 31;
    const int j   = jt * 8 + w;

    const float* __restrict__ wbase = whh_l + (size_t)dir * 4 * HH * HH;

    for (int i = tid; i < 32 * 128; i += 256) {
        int rw = i >> 7, k4 = i & 127;
        int gg = rw >> 3, jl = rw & 7;
        float4 v = *(const float4*)(wbase + (size_t)(gg * HH + jt * 8 + jl) * HH + k4 * 4);
        *(float4*)(ws + rw * 512 + k4 * 4) = v;
    }
    __syncthreads();

    const int sb  = tid >> 3;
    const int sg  = (tid >> 1) & 3;
    const int sj4 = tid & 1;

    float c_reg = 0.f;

    for (int t = 0; t < TT; t++) {
        const int p  = t & 1;
        const int tt = dir ? (TT - 1 - t) : t;

        if (t > 0) {
            __syncthreads();
            if (tid == 0) {
                __threadfence();
                unsigned a = atomicAdd(&g_bar_cnt[dir], 1u);
                if (a == 63u) {
                    g_bar_cnt[dir] = 0u;
                    __threadfence();
                    atomicExch(&g_bar_gen[dir], (unsigned)t);
                } else {
                    while (*(volatile unsigned*)&g_bar_gen[dir] < (unsigned)t) { }
                }
                __threadfence();
            }
            __syncthreads();
        }

        {
            const float* hsrc = g_h + (size_t)(p * 2 + dir) * (BB * HH);
            for (int i = tid; i < 32 * 128; i += 256) {
                int bb = i >> 7, k4 = i & 127;
                float4 v = *(const float4*)(hsrc + bb * 512 + k4 * 4);
                *(float4*)(hs + bb * 516 + k4 * 4) = v;
            }
        }
        {
            const float* ipg = g_inproj + ((size_t)tt * 32 + sb) * NPROJ
                               + dir * NGATE + sg * HH + jt * 8 + sj4 * 4;
            float4 v = *(const float4*)ipg;
            int rbase = sg * 8 + sj4 * 4;
            ips[(rbase + 0) * 33 + sb] = v.x;
            ips[(rbase + 1) * 33 + sb] = v.y;
            ips[(rbase + 2) * 33 + sb] = v.z;
            ips[(rbase + 3) * 33 + sb] = v.w;
        }
        __syncthreads();

        const ulonglong2* hp  = (const ulonglong2*)(hs + b * 516);
        const ulonglong2* w0p = (const ulonglong2*)(ws + (0 * 8 + w) * 512);
        const ulonglong2* w1p = (const ulonglong2*)(ws + (1 * 8 + w) * 512);
        const ulonglong2* w2p = (const ulonglong2*)(ws + (2 * 8 + w) * 512);
        const ulonglong2* w3p = (const ulonglong2*)(ws + (3 * 8 + w) * 512);

        u64 ac0 = 0, ac1 = 0, ac2 = 0, ac3 = 0, ac4 = 0, ac5 = 0, ac6 = 0, ac7 = 0;
#pragma unroll 8
        for (int k4 = 0; k4 < 128; k4++) {
            ulonglong2 h2 = hp[k4];
            ulonglong2 q0 = w0p[k4];
            ulonglong2 q1 = w1p[k4];
            ulonglong2 q2 = w2p[k4];
            ulonglong2 q3 = w3p[k4];
            FMA2(ac0, h2.x, q0.x);  FMA2(ac1, h2.y, q0.y);
            FMA2(ac2, h2.x, q1.x);  FMA2(ac3, h2.y, q1.y);
            FMA2(ac4, h2.x, q2.x);  FMA2(ac5, h2.y, q2.y);
            FMA2(ac6, h2.x, q3.x);  FMA2(ac7, h2.y, q3.y);
        }

        float gi = sum2(ac0) + sum2(ac1) + ips[(0 * 8 + w) * 33 + b];
        float gf = sum2(ac2) + sum2(ac3) + ips[(1 * 8 + w) * 33 + b];
        float gg = sum2(ac4) + sum2(ac5) + ips[(2 * 8 + w) * 33 + b];
        float go = sum2(ac6) + sum2(ac7) + ips[(3 * 8 + w) * 33 + b];

        gi = 1.f / (1.f + expf(-gi));
        gf = 1.f / (1.f + expf(-gf));
        gg = tanhf(gg);
        go = 1.f / (1.f + expf(-go));

        c_reg = gf * c_reg + gi * gg;
        float h = go * tanhf(c_reg);

        g_h[(size_t)((p ^ 1) * 2 + dir) * (BB * HH) + b * 512 + j] = h;

        size_t o = ((size_t)tt * 32 + b) * 1024 + dir * HH + j;
        if (layer == 0) {
            __nv_bfloat16 hh = __float2bfloat16(h);
            __nv_bfloat16 hl = __float2bfloat16(h - __bfloat162float(hh));
            g_h0_hi[o] = hh;
            g_h0_lo[o] = hl;
        } else {
            g_hout1[o] = h;
        }
    }
}

// -------------------- FC: logits[b][t][c] --------------------
__global__ void fc_kernel(const float* __restrict__ fcw, const float* __restrict__ fcb,
                          float* __restrict__ out) {
    int row = blockIdx.x;          // t*BB + b
    int t = row >> 5;
    int b = row & 31;
    int c = threadIdx.x >> 5;      // 0..23
    int lane = threadIdx.x & 31;

    const float4* h4 = (const float4*)(g_hout1 + (size_t)row * 1024);
    const float4* w4 = (const float4*)(fcw + (size_t)c * 1024);
    float s = 0.f;
#pragma unroll 4
    for (int k = lane; k < 256; k += 32) {
        float4 a = h4[k], w = w4[k];
        s += a.x * w.x + a.y * w.y + a.z * w.z + a.w * w.w;
    }
#pragma unroll
    for (int o = 16; o; o >>= 1) s += __shfl_xor_sync(0xffffffffu, s, o);
    if (lane == 0) out[((size_t)b * TT + t) * CC + c] = s + fcb[c];
}

// -------------------- CRF per-batch block --------------------
__global__ void crf_block(const float* __restrict__ em, const int* __restrict__ labels,
                          const float* __restrict__ st, const float* __restrict__ en,
                          const float* __restrict__ tr) {
    const int b = blockIdx.x;
    const int cn = threadIdx.x;    // 32 threads, 24 active for DP
    __shared__ float trs[24][25];
    __shared__ float alpha[25];
    __shared__ int   labs[TT];
    __shared__ float s_en[24], s_st[24];

    for (int i = cn; i < 576; i += 32) trs[i / 24][i % 24] = tr[i];
    if (cn < 24) { s_en[cn] = en[cn]; s_st[cn] = st[cn]; }
    for (int i = cn; i < TT; i += 32) labs[i] = labels[b * TT + i];
    __syncwarp();

    const float* emb_ = em + (size_t)b * TT * CC;
    if (cn < 24) alpha[cn] = s_st[cn] + emb_[cn];
    __syncwarp();

    for (int t = 1; t < TT; t++) {
        float anew = 0.f;
        if (cn < 24) {
            float m = -1e30f;
#pragma unroll
            for (int cp = 0; cp < 24; cp++) m = fmaxf(m, alpha[cp] + trs[cp][cn]);
            float s = 0.f;
#pragma unroll
            for (int cp = 0; cp < 24; cp++) s += __expf(alpha[cp] + trs[cp][cn] - m);
            anew = m + __logf(s) + emb_[t * CC + cn];
        }
        __syncwarp();
        if (cn < 24) alpha[cn] = anew;
        __syncwarp();
    }

    // gold path score, warp-parallel over t
    float gs = 0.f;
    for (int t = cn; t < TT; t += 32) {
        int tg = labs[t];
        gs += emb_[t * CC + tg];
        if (t > 0) gs += trs[labs[t - 1]][tg];
    }
#pragma unroll
    for (int o = 16; o; o >>= 1) gs += __shfl_xor_sync(0xffffffffu, gs, o);

    if (cn == 0) {
        float m = -1e30f;
        for (int c = 0; c < 24; c++) m = fmaxf(m, alpha[c] + s_en[c]);
        float s = 0.f;
        for (int c = 0; c < 24; c++) s += __expf(alpha[c] + s_en[c] - m);
        float logZ = m + __logf(s);
        float num = gs + s_st[labs[0]] + s_en[labs[TT - 1]];
        g_crf_partial[b] = logZ - num;
    }
}

__global__ void crf_final(float* __restrict__ loss_out) {
    if (threadIdx.x == 0) {
        float L = 0.f;
        for (int b = 0; b < BB; b++) L += g_crf_partial[b];
        loss_out[0] = L;   // -llh
    }
}

// -------------------- launch --------------------
extern "C" void kernel_launch(void* const* d_in, const int* in_sizes, int n_in,
                              void* d_out, int out_size) {
    const int*   x         = (const int*)d_in[0];
    const int*   labels    = (const int*)d_in[1];
    const float* emb       = (const float*)d_in[2];
    const float* w_ih      = (const float*)d_in[3];
    const float* w_hh      = (const float*)d_in[4];
    const float* b_ih      = (const float*)d_in[5];
    const float* b_hh      = (const float*)d_in[6];
    const float* fc_w      = (const float*)d_in[7];
    const float* fc_b      = (const float*)d_in[8];
    const float* crf_start = (const float*)d_in[9];
    const float* crf_end   = (const float*)d_in[10];
    const float* crf_trans = (const float*)d_in[11];
    float* out = (float*)d_out;

    (void)in_sizes; (void)n_in; (void)out_size;

    cudaFuncSetAttribute(lstm_layer_persist,
                         cudaFuncAttributeMaxDynamicSharedMemorySize, L_SMEM_BYTES);
    cudaFuncSetAttribute(gemm_mma,
                         cudaFuncAttributeMaxDynamicSharedMemorySize, GM_SMEM);

    // 1. embedding gather + bf16 split
    gather_split<<<MROWS, 256>>>(x, emb);

    // 2. weight split (both layers)
    wconv<<<8192, 256>>>(w_ih);

    // 3. per-layer: tensor-core input projection, then persistent recurrence
    for (int l = 0; l < 2; l++) {
        const float* whh_l = w_hh + (size_t)l * 2 * NGATE * HH;
        const float* bih_l = b_ih + (size_t)l * NPROJ;
        const float* bhh_l = b_hh + (size_t)l * NPROJ;

        gemm_mma<<<dim3(NPROJ / 128, MROWS / 128), 256, GM_SMEM>>>(l, bih_l, bhh_l);
        zero_state_kernel<<<256, 256>>>();
        lstm_layer_persist<<<128, 256, L_SMEM_BYTES>>>(whh_l, l);
    }

    // 4. FC -> logits into d_out as [b][t][c]
    fc_kernel<<<MROWS, 768>>>(fc_w, fc_b, out);

    // 5. CRF loss -> d_out[B*T*C]
    crf_block<<<BB, 32>>>(out, labels, crf_start, crf_end, crf_trans);
    crf_final<<<1, 32>>>(out + (size_t)BB * TT * CC);
}